// round 2
// baseline (speedup 1.0000x reference)
#include <cuda_runtime.h>

#define Bn 64
#define Tn 128
#define Sn 128
#define Cn 512
#define Hn 8
#define DHn 64
#define FFn 2048
#define Ln 6

// ---------------- scratch (device globals; no allocation allowed) ----------------
__device__ float g_q[Bn*Hn*Tn*DHn];
__device__ float g_k[Bn*Hn*Sn*DHn];
__device__ float g_v[Bn*Hn*Sn*DHn];
__device__ float g_attn[Bn*Tn*Cn];      // attention / FF2 output (residual source)
__device__ float g_h[(size_t)Bn*Tn*FFn]; // FF hidden

// ---------------- QKV projection: per (b,h) GEMM  M=128, N=64, K=512 ----------------
// grid (B*H, 3), block 256. blockIdx.y: 0=Q(from src_q), 1=K(from src_kv), 2=V(from src_kv)
__global__ __launch_bounds__(256) void qkv_proj_kernel(
    const float* __restrict__ src_q, const float* __restrict__ src_kv,
    const float* __restrict__ wq, const float* __restrict__ bq,
    const float* __restrict__ wk, const float* __restrict__ bk,
    const float* __restrict__ wv, const float* __restrict__ bv)
{
    __shared__ float As[16][136];   // k-major A tile: As[kk][row], padded for alignment
    __shared__ float Bs[16][64];

    int bh = blockIdx.x;
    int h = bh & (Hn - 1);
    int b = bh >> 3;

    const float* src; const float* w; const float* bias; float* outp;
    if (blockIdx.y == 0)      { src = src_q  + (size_t)b*Tn*Cn; w = wq; bias = bq; outp = g_q; }
    else if (blockIdx.y == 1) { src = src_kv + (size_t)b*Sn*Cn; w = wk; bias = bk; outp = g_k; }
    else                      { src = src_kv + (size_t)b*Sn*Cn; w = wv; bias = bv; outp = g_v; }
    w    += (size_t)h * Cn * DHn;   // [C, DH] row-major
    bias += (size_t)h * DHn;
    outp += (size_t)bh * Tn * DHn;  // [T(=S), DH]

    int tid = threadIdx.x;
    int tx = tid & 15;        // col group: cols tx*4 .. tx*4+3
    int ty = tid >> 4;        // row group: rows ty*8 .. ty*8+7

    float acc[8][4];
    #pragma unroll
    for (int i = 0; i < 8; i++)
        #pragma unroll
        for (int j = 0; j < 4; j++) acc[i][j] = 0.f;

    for (int k0 = 0; k0 < Cn; k0 += 16) {
        #pragma unroll
        for (int j = 0; j < 8; j++) {           // 2048 elems of A
            int e = tid + j * 256;
            int r = e >> 4, kk = e & 15;
            As[kk][r] = src[r * Cn + k0 + kk];
        }
        #pragma unroll
        for (int j = 0; j < 4; j++) {           // 1024 elems of W
            int e = tid + j * 256;
            int kk = e >> 6, n = e & 63;
            Bs[kk][n] = w[(k0 + kk) * DHn + n];
        }
        __syncthreads();
        #pragma unroll
        for (int kk = 0; kk < 16; kk++) {
            float4 a0 = *(const float4*)&As[kk][ty * 8];
            float4 a1 = *(const float4*)&As[kk][ty * 8 + 4];
            float4 b4 = *(const float4*)&Bs[kk][tx * 4];
            float a[8] = {a0.x, a0.y, a0.z, a0.w, a1.x, a1.y, a1.z, a1.w};
            float bb[4] = {b4.x, b4.y, b4.z, b4.w};
            #pragma unroll
            for (int i = 0; i < 8; i++)
                #pragma unroll
                for (int j = 0; j < 4; j++)
                    acc[i][j] += a[i] * bb[j];
        }
        __syncthreads();
    }

    #pragma unroll
    for (int i = 0; i < 8; i++) {
        int r = ty * 8 + i;
        #pragma unroll
        for (int j = 0; j < 4; j++) {
            int c = tx * 4 + j;
            outp[r * DHn + c] = acc[i][j] + bias[c];
        }
    }
}

// ---------------- fused attention per (b,h): softmax(QK^T/8)V ----------------
// grid B*H, block 256, dynamic smem
#define QP 65                       // padded row stride for Q/K/V tiles
#define PP 129                      // padded row stride for P
#define ATTN_SMEM ((3*128*QP + 128*PP) * (int)sizeof(float))  // 165888 B

__global__ __launch_bounds__(256) void attn_kernel()
{
    extern __shared__ float sm[];
    float* Qs = sm;
    float* Ks = sm + 128 * QP;
    float* Vs = sm + 2 * 128 * QP;
    float* Ps = sm + 3 * 128 * QP;

    int bh = blockIdx.x;
    int h = bh & (Hn - 1);
    int b = bh >> 3;
    int tid = threadIdx.x;

    const float* qg = g_q + (size_t)bh * Tn * DHn;
    const float* kg = g_k + (size_t)bh * Sn * DHn;
    const float* vg = g_v + (size_t)bh * Sn * DHn;

    for (int e = tid; e < Tn * DHn; e += 256) {
        int r = e >> 6, d = e & 63;
        Qs[r * QP + d] = qg[e];
        Ks[r * QP + d] = kg[e];
        Vs[r * QP + d] = vg[e];
    }
    __syncthreads();

    // scores: 128x128, thread = 8 rows x 8 cols
    int tx = tid & 15, ty = tid >> 4;
    {
        int r0 = ty * 8, c0 = tx * 8;
        float acc[8][8];
        #pragma unroll
        for (int i = 0; i < 8; i++)
            #pragma unroll
            for (int j = 0; j < 8; j++) acc[i][j] = 0.f;
        for (int d = 0; d < DHn; d++) {
            float a[8], bb[8];
            #pragma unroll
            for (int i = 0; i < 8; i++) a[i] = Qs[(r0 + i) * QP + d];
            #pragma unroll
            for (int j = 0; j < 8; j++) bb[j] = Ks[(c0 + j) * QP + d];
            #pragma unroll
            for (int i = 0; i < 8; i++)
                #pragma unroll
                for (int j = 0; j < 8; j++)
                    acc[i][j] += a[i] * bb[j];
        }
        #pragma unroll
        for (int i = 0; i < 8; i++)
            #pragma unroll
            for (int j = 0; j < 8; j++)
                Ps[(r0 + i) * PP + c0 + j] = acc[i][j] * 0.125f;
    }
    __syncthreads();

    // softmax over each row (threads 0..127, one row each)
    if (tid < Tn) {
        float* p = Ps + tid * PP;
        float mx = -1e30f;
        for (int j = 0; j < Sn; j++) mx = fmaxf(mx, p[j]);
        float ssum = 0.f;
        for (int j = 0; j < Sn; j++) { float e = __expf(p[j] - mx); p[j] = e; ssum += e; }
        float inv = 1.f / ssum;
        for (int j = 0; j < Sn; j++) p[j] *= inv;
    }
    __syncthreads();

    // O = P @ V : 128x64, thread = 8 rows x 4 cols
    {
        int r0 = ty * 8, c0 = tx * 4;
        float o[8][4];
        #pragma unroll
        for (int i = 0; i < 8; i++)
            #pragma unroll
            for (int j = 0; j < 4; j++) o[i][j] = 0.f;
        for (int k = 0; k < Sn; k++) {
            float p[8], v[4];
            #pragma unroll
            for (int i = 0; i < 8; i++) p[i] = Ps[(r0 + i) * PP + k];
            #pragma unroll
            for (int j = 0; j < 4; j++) v[j] = Vs[k * QP + c0 + j];
            #pragma unroll
            for (int i = 0; i < 8; i++)
                #pragma unroll
                for (int j = 0; j < 4; j++)
                    o[i][j] += p[i] * v[j];
        }
        float* og = g_attn + (size_t)b * Tn * Cn + (size_t)h * DHn;
        #pragma unroll
        for (int i = 0; i < 8; i++)
            #pragma unroll
            for (int j = 0; j < 4; j++)
                og[(r0 + i) * Cn + c0 + j] = o[i][j];
    }
}

// ---------------- residual add + joint (T,C) LayerNorm, one block per batch ----------------
__global__ __launch_bounds__(256) void add_ln_kernel(float* __restrict__ x)
{
    int b = blockIdx.x;
    float* xb = x + (size_t)b * Tn * Cn;
    const float* rb = g_attn + (size_t)b * Tn * Cn;
    int tid = threadIdx.x;

    float s = 0.f, s2 = 0.f;
    for (int i = tid; i < Tn * Cn; i += 256) {
        float y = xb[i] + rb[i];
        xb[i] = y;
        s += y; s2 += y * y;
    }
    __shared__ float sh[512];
    sh[tid] = s; sh[256 + tid] = s2;
    __syncthreads();
    for (int st = 128; st > 0; st >>= 1) {
        if (tid < st) { sh[tid] += sh[tid + st]; sh[256 + tid] += sh[256 + tid + st]; }
        __syncthreads();
    }
    const float invN = 1.f / (Tn * Cn);
    float mu  = sh[0] * invN;
    float var = sh[256] * invN - mu * mu;
    float inv = rsqrtf(var + 1e-5f);
    for (int i = tid; i < Tn * Cn; i += 256)
        xb[i] = (xb[i] - mu) * inv;
}

// ---------------- generic FF GEMM: out = [relu](A[M,K] @ W[K,N] + bias) ----------------
// MODE 0: A = param (x), out = g_h, ReLU       (FF1)
// MODE 1: A = g_h, out = g_attn, no ReLU       (FF2)
template<int MODE>
__global__ __launch_bounds__(256) void gemm_kernel(
    const float* __restrict__ Ap, const float* __restrict__ W,
    const float* __restrict__ bias, int M, int N, int K)
{
    const float* A = (MODE == 0) ? Ap : (const float*)g_h;
    float* outp    = (MODE == 0) ? g_h : g_attn;

    __shared__ float As[16][72];    // k-major: As[kk][row]
    __shared__ float Bs[16][64];

    int tid = threadIdx.x;
    int tx = tid & 15, ty = tid >> 4;
    int rowTile = blockIdx.y * 64, colTile = blockIdx.x * 64;
    const float* Ab = A + (size_t)rowTile * K;
    const float* Wb = W + colTile;

    float acc[4][4];
    #pragma unroll
    for (int i = 0; i < 4; i++)
        #pragma unroll
        for (int j = 0; j < 4; j++) acc[i][j] = 0.f;

    for (int k0 = 0; k0 < K; k0 += 16) {
        #pragma unroll
        for (int j = 0; j < 4; j++) {
            int e = tid + j * 256;
            int r = e >> 4, kk = e & 15;
            As[kk][r] = Ab[(size_t)r * K + k0 + kk];
        }
        #pragma unroll
        for (int j = 0; j < 4; j++) {
            int e = tid + j * 256;
            int kk = e >> 6, n = e & 63;
            Bs[kk][n] = Wb[(size_t)(k0 + kk) * N + n];
        }
        __syncthreads();
        #pragma unroll
        for (int kk = 0; kk < 16; kk++) {
            float4 a4 = *(const float4*)&As[kk][ty * 4];
            float4 b4 = *(const float4*)&Bs[kk][tx * 4];
            float a[4] = {a4.x, a4.y, a4.z, a4.w};
            float bb[4] = {b4.x, b4.y, b4.z, b4.w};
            #pragma unroll
            for (int i = 0; i < 4; i++)
                #pragma unroll
                for (int j = 0; j < 4; j++)
                    acc[i][j] += a[i] * bb[j];
        }
        __syncthreads();
    }

    #pragma unroll
    for (int i = 0; i < 4; i++) {
        int r = rowTile + ty * 4 + i;
        #pragma unroll
        for (int j = 0; j < 4; j++) {
            int c = colTile + tx * 4 + j;
            float v = acc[i][j] + bias[c];
            if (MODE == 0) v = fmaxf(v, 0.f);
            outp[(size_t)r * N + c] = v;
        }
    }
}

// ---------------- driver ----------------
extern "C" void kernel_launch(void* const* d_in, const int* in_sizes, int n_in,
                              void* d_out, int out_size)
{
    const float* x     = (const float*)d_in[0];
    const float* enc   = (const float*)d_in[1];
    const float* sa_wq = (const float*)d_in[2];  const float* sa_bq = (const float*)d_in[3];
    const float* sa_wk = (const float*)d_in[4];  const float* sa_bk = (const float*)d_in[5];
    const float* sa_wv = (const float*)d_in[6];  const float* sa_bv = (const float*)d_in[7];
    const float* ca_wq = (const float*)d_in[8];  const float* ca_bq = (const float*)d_in[9];
    const float* ca_wk = (const float*)d_in[10]; const float* ca_bk = (const float*)d_in[11];
    const float* ca_wv = (const float*)d_in[12]; const float* ca_bv = (const float*)d_in[13];
    const float* ff_w1 = (const float*)d_in[14]; const float* ff_b1 = (const float*)d_in[15];
    const float* ff_w2 = (const float*)d_in[16]; const float* ff_b2 = (const float*)d_in[17];
    float* out = (float*)d_out;

    cudaFuncSetAttribute(attn_kernel, cudaFuncAttributeMaxDynamicSharedMemorySize, ATTN_SMEM);

    // x lives in d_out for the whole pipeline (final result is x)
    cudaMemcpyAsync(out, x, sizeof(float) * Bn * Tn * Cn, cudaMemcpyDeviceToDevice);

    const size_t WS = (size_t)Hn * Cn * DHn;   // per-layer per-proj weight stride
    const size_t BS = (size_t)Hn * DHn;        // per-layer bias stride

    for (int l = 0; l < Ln; l++) {
        // ---- self attention ----
        qkv_proj_kernel<<<dim3(Bn * Hn, 3), 256>>>(out, out,
            sa_wq + l * WS, sa_bq + l * BS,
            sa_wk + l * WS, sa_bk + l * BS,
            sa_wv + l * WS, sa_bv + l * BS);
        attn_kernel<<<Bn * Hn, 256, ATTN_SMEM>>>();
        add_ln_kernel<<<Bn, 256>>>(out);

        // ---- cross attention (k/v from encoder output) ----
        qkv_proj_kernel<<<dim3(Bn * Hn, 3), 256>>>(out, enc,
            ca_wq + l * WS, ca_bq + l * BS,
            ca_wk + l * WS, ca_bk + l * BS,
            ca_wv + l * WS, ca_bv + l * BS);
        attn_kernel<<<Bn * Hn, 256, ATTN_SMEM>>>();
        add_ln_kernel<<<Bn, 256>>>(out);

        // ---- feed forward ----
        gemm_kernel<0><<<dim3(FFn / 64, (Bn * Tn) / 64), 256>>>(
            out, ff_w1 + (size_t)l * Cn * FFn, ff_b1 + (size_t)l * FFn,
            Bn * Tn, FFn, Cn);
        gemm_kernel<1><<<dim3(Cn / 64, (Bn * Tn) / 64), 256>>>(
            nullptr, ff_w2 + (size_t)l * FFn * Cn, ff_b2 + (size_t)l * Cn,
            Bn * Tn, Cn, FFn);
        add_ln_kernel<<<Bn, 256>>>(out);
    }
}

// round 3
// speedup vs baseline: 2.5210x; 2.5210x over previous
#include <cuda_runtime.h>

#define Bn 64
#define Tn 128
#define Sn 128
#define Cn 512
#define Hn 8
#define DHn 64
#define FFn 2048
#define Ln 6

// ---------------- scratch (device globals; no allocation allowed) ----------------
__device__ float g_q[Bn*Hn*Tn*DHn];
__device__ float g_k[Bn*Hn*Sn*DHn];
__device__ float g_v[Bn*Hn*Sn*DHn];
__device__ float g_attn[Bn*Tn*Cn];       // attention / FF2 output (residual source)
__device__ float g_h[(size_t)Bn*Tn*FFn]; // FF hidden

// ---------------- tf32 helpers ----------------
__device__ __forceinline__ unsigned f2tf(float f) {
    unsigned u;
    asm("cvt.rna.tf32.f32 %0, %1;" : "=r"(u) : "f"(f));
    return u;
}
__device__ __forceinline__ void mma8(float c[4], const unsigned a[4], const unsigned b[2]) {
    asm volatile("mma.sync.aligned.m16n8k8.row.col.f32.tf32.tf32.f32 "
        "{%0,%1,%2,%3}, {%4,%5,%6,%7}, {%8,%9}, {%0,%1,%2,%3};"
        : "+f"(c[0]), "+f"(c[1]), "+f"(c[2]), "+f"(c[3])
        : "r"(a[0]), "r"(a[1]), "r"(a[2]), "r"(a[3]), "r"(b[0]), "r"(b[1]));
}

// ---------------- QKV projection: per (b,h) GEMM  M=128, N=64, K=512 (tf32 mma) ----------
// grid (B*H, 3), block 256 (8 warps: 4 along M x 2 along N; warp tile 32x32)
__global__ __launch_bounds__(256) void qkv_proj_kernel(
    const float* __restrict__ src_q, const float* __restrict__ src_kv,
    const float* __restrict__ wq, const float* __restrict__ bq,
    const float* __restrict__ wk, const float* __restrict__ bk,
    const float* __restrict__ wv, const float* __restrict__ bv)
{
    __shared__ float As[128*36];   // [m][k], stride 36 -> conflict-free frag loads
    __shared__ float Bs[64*36];    // [n][k], stride 36

    int bh = blockIdx.x;
    int h = bh & (Hn - 1);
    int b = bh >> 3;

    const float* src; const float* w; const float* bias; float* outp;
    if (blockIdx.y == 0)      { src = src_q  + (size_t)b*Tn*Cn; w = wq; bias = bq; outp = g_q; }
    else if (blockIdx.y == 1) { src = src_kv + (size_t)b*Sn*Cn; w = wk; bias = bk; outp = g_k; }
    else                      { src = src_kv + (size_t)b*Sn*Cn; w = wv; bias = bv; outp = g_v; }
    w    += (size_t)h * Cn * DHn;
    bias += (size_t)h * DHn;
    outp += (size_t)bh * Tn * DHn;

    int tid = threadIdx.x, wid = tid >> 5, lane = tid & 31;
    int wm = wid >> 1, wn = wid & 1;     // 4 x 2 warp grid
    int g = lane >> 2, t = lane & 3;

    float acc[2][4][4];
    #pragma unroll
    for (int i = 0; i < 2; i++)
        #pragma unroll
        for (int j = 0; j < 4; j++)
            #pragma unroll
            for (int q = 0; q < 4; q++) acc[i][j][q] = 0.f;

    for (int k0 = 0; k0 < Cn; k0 += 32) {
        #pragma unroll
        for (int j = 0; j < 16; j++) {
            int e = tid + j * 256; int r = e >> 5, kk = e & 31;
            As[r*36 + kk] = __uint_as_float(f2tf(src[(size_t)r*Cn + k0 + kk]));
        }
        #pragma unroll
        for (int j = 0; j < 8; j++) {
            int e = tid + j * 256; int kk = e >> 6, n = e & 63;
            Bs[n*36 + kk] = __uint_as_float(f2tf(w[(size_t)(k0+kk)*DHn + n]));
        }
        __syncthreads();
        const unsigned* Au = (const unsigned*)As;
        const unsigned* Bu = (const unsigned*)Bs;
        #pragma unroll
        for (int ks = 0; ks < 4; ks++) {
            unsigned a[2][4], bf[4][2];
            int c = ks*8 + t;
            #pragma unroll
            for (int i = 0; i < 2; i++) {
                int r = wm*32 + i*16 + g;
                a[i][0] = Au[r*36 + c];
                a[i][1] = Au[(r+8)*36 + c];
                a[i][2] = Au[r*36 + c + 4];
                a[i][3] = Au[(r+8)*36 + c + 4];
            }
            #pragma unroll
            for (int j = 0; j < 4; j++) {
                int n = wn*32 + j*8 + g;
                bf[j][0] = Bu[n*36 + c];
                bf[j][1] = Bu[n*36 + c + 4];
            }
            #pragma unroll
            for (int i = 0; i < 2; i++)
                #pragma unroll
                for (int j = 0; j < 4; j++)
                    mma8(acc[i][j], a[i], bf[j]);
        }
        __syncthreads();
    }

    #pragma unroll
    for (int i = 0; i < 2; i++) {
        int r0 = wm*32 + i*16 + g;
        #pragma unroll
        for (int j = 0; j < 4; j++) {
            int c = wn*32 + j*8 + 2*t;
            float b0 = bias[c], b1 = bias[c+1];
            *(float2*)&outp[(size_t)r0*DHn + c]     = make_float2(acc[i][j][0]+b0, acc[i][j][1]+b1);
            *(float2*)&outp[(size_t)(r0+8)*DHn + c] = make_float2(acc[i][j][2]+b0, acc[i][j][3]+b1);
        }
    }
}

// ---------------- fused attention per (b,h): softmax(QK^T/8)V with tf32 mma -----------
#define QS 68
#define PS 132
#define ATTN_SMEM ((3*128*QS + 128*PS) * (int)sizeof(float))   // 172032 B

__global__ __launch_bounds__(256) void attn_kernel()
{
    extern __shared__ float sm[];
    float* Qs = sm;
    float* Ks = sm + 128*QS;
    float* Vs = sm + 2*128*QS;
    float* Ps = sm + 3*128*QS;

    int bh = blockIdx.x;
    int h = bh & (Hn - 1);
    int b = bh >> 3;
    int tid = threadIdx.x, wid = tid >> 5, lane = tid & 31;
    int g = lane >> 2, t = lane & 3;

    const float* qg = g_q + (size_t)bh * Tn * DHn;
    const float* kg = g_k + (size_t)bh * Sn * DHn;
    const float* vg = g_v + (size_t)bh * Sn * DHn;

    // stage Q (pre-scaled by 1/8, exact in tf32), K, V as tf32 bit patterns
    for (int e = tid; e < Tn * DHn; e += 256) {
        int r = e >> 6, d = e & 63;
        Qs[r*QS + d] = __uint_as_float(f2tf(qg[e] * 0.125f));
        Ks[r*QS + d] = __uint_as_float(f2tf(kg[e]));
        Vs[r*QS + d] = __uint_as_float(f2tf(vg[e]));
    }
    __syncthreads();

    // ---- scores = (Q/8) @ K^T : 128x128, K-dim 64. warps 2(M)x4(N), warp 64x32 ----
    {
        int wm = wid >> 2, wn = wid & 3;
        float acc[4][4][4];
        #pragma unroll
        for (int i = 0; i < 4; i++)
            #pragma unroll
            for (int j = 0; j < 4; j++)
                #pragma unroll
                for (int q = 0; q < 4; q++) acc[i][j][q] = 0.f;

        const unsigned* Qu = (const unsigned*)Qs;
        const unsigned* Ku = (const unsigned*)Ks;
        #pragma unroll
        for (int ks = 0; ks < 8; ks++) {
            int c = ks*8 + t;
            unsigned a[4][4], bf[4][2];
            #pragma unroll
            for (int i = 0; i < 4; i++) {
                int r = wm*64 + i*16 + g;
                a[i][0] = Qu[r*QS + c];
                a[i][1] = Qu[(r+8)*QS + c];
                a[i][2] = Qu[r*QS + c + 4];
                a[i][3] = Qu[(r+8)*QS + c + 4];
            }
            #pragma unroll
            for (int j = 0; j < 4; j++) {
                int n = wn*32 + j*8 + g;
                bf[j][0] = Ku[n*QS + c];
                bf[j][1] = Ku[n*QS + c + 4];
            }
            #pragma unroll
            for (int i = 0; i < 4; i++)
                #pragma unroll
                for (int j = 0; j < 4; j++)
                    mma8(acc[i][j], a[i], bf[j]);
        }
        #pragma unroll
        for (int i = 0; i < 4; i++) {
            int r0 = wm*64 + i*16 + g;
            #pragma unroll
            for (int j = 0; j < 4; j++) {
                int c = wn*32 + j*8 + 2*t;
                *(float2*)&Ps[r0*PS + c]     = make_float2(acc[i][j][0], acc[i][j][1]);
                *(float2*)&Ps[(r0+8)*PS + c] = make_float2(acc[i][j][2], acc[i][j][3]);
            }
        }
    }
    __syncthreads();

    // ---- softmax: 2 threads per row ----
    {
        int row = tid >> 1;
        float* p = Ps + row*PS + (tid & 1) * 64;
        float mx = -1e30f;
        #pragma unroll 8
        for (int j = 0; j < 64; j++) mx = fmaxf(mx, p[j]);
        mx = fmaxf(mx, __shfl_xor_sync(0xffffffffu, mx, 1));
        float s = 0.f;
        #pragma unroll 8
        for (int j = 0; j < 64; j++) { float e = __expf(p[j] - mx); p[j] = e; s += e; }
        s += __shfl_xor_sync(0xffffffffu, s, 1);
        float inv = 1.f / s;
        #pragma unroll 8
        for (int j = 0; j < 64; j++) p[j] = __uint_as_float(f2tf(p[j] * inv));
    }
    __syncthreads();

    // ---- O = P @ V : 128x64, K-dim 128. warps 4(M)x2(N), warp 32x32 ----
    {
        int wm = wid >> 1, wn = wid & 1;
        float acc[2][4][4];
        #pragma unroll
        for (int i = 0; i < 2; i++)
            #pragma unroll
            for (int j = 0; j < 4; j++)
                #pragma unroll
                for (int q = 0; q < 4; q++) acc[i][j][q] = 0.f;

        const unsigned* Pu = (const unsigned*)Ps;
        const unsigned* Vu = (const unsigned*)Vs;
        #pragma unroll
        for (int ks = 0; ks < 16; ks++) {
            int c = ks*8 + t;
            unsigned a[2][4], bf[4][2];
            #pragma unroll
            for (int i = 0; i < 2; i++) {
                int r = wm*32 + i*16 + g;
                a[i][0] = Pu[r*PS + c];
                a[i][1] = Pu[(r+8)*PS + c];
                a[i][2] = Pu[r*PS + c + 4];
                a[i][3] = Pu[(r+8)*PS + c + 4];
            }
            #pragma unroll
            for (int j = 0; j < 4; j++) {
                int n = wn*32 + j*8 + g;
                bf[j][0] = Vu[c*QS + n];
                bf[j][1] = Vu[(c+4)*QS + n];
            }
            #pragma unroll
            for (int i = 0; i < 2; i++)
                #pragma unroll
                for (int j = 0; j < 4; j++)
                    mma8(acc[i][j], a[i], bf[j]);
        }

        float* og = g_attn + (size_t)b * Tn * Cn + (size_t)h * DHn;
        #pragma unroll
        for (int i = 0; i < 2; i++) {
            int r0 = wm*32 + i*16 + g;
            #pragma unroll
            for (int j = 0; j < 4; j++) {
                int c = wn*32 + j*8 + 2*t;
                *(float2*)&og[(size_t)r0*Cn + c]     = make_float2(acc[i][j][0], acc[i][j][1]);
                *(float2*)&og[(size_t)(r0+8)*Cn + c] = make_float2(acc[i][j][2], acc[i][j][3]);
            }
        }
    }
}

// ---------------- residual add + joint (T,C) LayerNorm, one block per batch ------------
__global__ __launch_bounds__(1024) void add_ln_kernel(float* __restrict__ x)
{
    int b = blockIdx.x;
    float4* x4 = (float4*)(x + (size_t)b * Tn * Cn);
    const float4* r4 = (const float4*)(g_attn + (size_t)b * Tn * Cn);
    int tid = threadIdx.x, lane = tid & 31, wid = tid >> 5;
    const int N4 = Tn * Cn / 4;  // 16384

    float s = 0.f, s2 = 0.f;
    for (int i = tid; i < N4; i += 1024) {
        float4 a = x4[i], r = r4[i];
        a.x += r.x; a.y += r.y; a.z += r.z; a.w += r.w;
        x4[i] = a;
        s  += a.x + a.y + a.z + a.w;
        s2 += a.x*a.x + a.y*a.y + a.z*a.z + a.w*a.w;
    }
    #pragma unroll
    for (int o = 16; o > 0; o >>= 1) {
        s  += __shfl_xor_sync(0xffffffffu, s, o);
        s2 += __shfl_xor_sync(0xffffffffu, s2, o);
    }
    __shared__ float sa[32], sb[32], stat[2];
    if (lane == 0) { sa[wid] = s; sb[wid] = s2; }
    __syncthreads();
    if (tid < 32) {
        s = sa[tid]; s2 = sb[tid];
        #pragma unroll
        for (int o = 16; o > 0; o >>= 1) {
            s  += __shfl_xor_sync(0xffffffffu, s, o);
            s2 += __shfl_xor_sync(0xffffffffu, s2, o);
        }
        if (tid == 0) {
            const float invN = 1.f / (Tn * Cn);
            float mu  = s * invN;
            float var = s2 * invN - mu * mu;
            stat[0] = mu;
            stat[1] = rsqrtf(var + 1e-5f);
        }
    }
    __syncthreads();
    float mu = stat[0], inv = stat[1];
    for (int i = tid; i < N4; i += 1024) {
        float4 a = x4[i];
        a.x = (a.x - mu) * inv; a.y = (a.y - mu) * inv;
        a.z = (a.z - mu) * inv; a.w = (a.w - mu) * inv;
        x4[i] = a;
    }
}

// ---------------- FF GEMM (tf32 mma): out = [relu](A[M,K] @ W[K,N] + bias) -------------
// block tile 128x128, 8 warps (2 M x 4 N), warp tile 64x32
// MODE 0: A = param (x), out = g_h, ReLU   (FF1)
// MODE 1: A = g_h, out = g_attn, no ReLU   (FF2)
template<int MODE>
__global__ __launch_bounds__(256) void gemm_tf32_kernel(
    const float* __restrict__ Ap, const float* __restrict__ W,
    const float* __restrict__ bias, int M, int N, int K)
{
    const float* A = (MODE == 0) ? Ap : (const float*)g_h;
    float* outp    = (MODE == 0) ? g_h : g_attn;

    __shared__ float As[128*36];   // [m][k] stride 36
    __shared__ float Bs[128*36];   // [n][k] stride 36

    int tid = threadIdx.x, wid = tid >> 5, lane = tid & 31;
    int wm = wid >> 2, wn = wid & 3;     // 2 x 4 warps
    int g = lane >> 2, t = lane & 3;
    int rowTile = blockIdx.y * 128, colTile = blockIdx.x * 128;

    float acc[4][4][4];
    #pragma unroll
    for (int i = 0; i < 4; i++)
        #pragma unroll
        for (int j = 0; j < 4; j++)
            #pragma unroll
            for (int q = 0; q < 4; q++) acc[i][j][q] = 0.f;

    for (int k0 = 0; k0 < K; k0 += 32) {
        #pragma unroll
        for (int j = 0; j < 16; j++) {
            int e = tid + j * 256; int r = e >> 5, kk = e & 31;
            As[r*36 + kk] = __uint_as_float(f2tf(A[(size_t)(rowTile + r)*K + k0 + kk]));
        }
        #pragma unroll
        for (int j = 0; j < 16; j++) {
            int e = tid + j * 256; int kk = e >> 7, n = e & 127;
            Bs[n*36 + kk] = __uint_as_float(f2tf(W[(size_t)(k0 + kk)*N + colTile + n]));
        }
        __syncthreads();
        const unsigned* Au = (const unsigned*)As;
        const unsigned* Bu = (const unsigned*)Bs;
        #pragma unroll
        for (int ks = 0; ks < 4; ks++) {
            int c = ks*8 + t;
            unsigned a[4][4], bf[4][2];
            #pragma unroll
            for (int i = 0; i < 4; i++) {
                int r = wm*64 + i*16 + g;
                a[i][0] = Au[r*36 + c];
                a[i][1] = Au[(r+8)*36 + c];
                a[i][2] = Au[r*36 + c + 4];
                a[i][3] = Au[(r+8)*36 + c + 4];
            }
            #pragma unroll
            for (int j = 0; j < 4; j++) {
                int n = wn*32 + j*8 + g;
                bf[j][0] = Bu[n*36 + c];
                bf[j][1] = Bu[n*36 + c + 4];
            }
            #pragma unroll
            for (int i = 0; i < 4; i++)
                #pragma unroll
                for (int j = 0; j < 4; j++)
                    mma8(acc[i][j], a[i], bf[j]);
        }
        __syncthreads();
    }

    #pragma unroll
    for (int i = 0; i < 4; i++) {
        int r0 = rowTile + wm*64 + i*16 + g;
        #pragma unroll
        for (int j = 0; j < 4; j++) {
            int c = colTile + wn*32 + j*8 + 2*t;
            float b0 = bias[c], b1 = bias[c+1];
            float v0 = acc[i][j][0] + b0, v1 = acc[i][j][1] + b1;
            float v2 = acc[i][j][2] + b0, v3 = acc[i][j][3] + b1;
            if (MODE == 0) {
                v0 = fmaxf(v0, 0.f); v1 = fmaxf(v1, 0.f);
                v2 = fmaxf(v2, 0.f); v3 = fmaxf(v3, 0.f);
            }
            *(float2*)&outp[(size_t)r0*N + c]     = make_float2(v0, v1);
            *(float2*)&outp[(size_t)(r0+8)*N + c] = make_float2(v2, v3);
        }
    }
}

// ---------------- driver ----------------
extern "C" void kernel_launch(void* const* d_in, const int* in_sizes, int n_in,
                              void* d_out, int out_size)
{
    const float* x     = (const float*)d_in[0];
    const float* enc   = (const float*)d_in[1];
    const float* sa_wq = (const float*)d_in[2];  const float* sa_bq = (const float*)d_in[3];
    const float* sa_wk = (const float*)d_in[4];  const float* sa_bk = (const float*)d_in[5];
    const float* sa_wv = (const float*)d_in[6];  const float* sa_bv = (const float*)d_in[7];
    const float* ca_wq = (const float*)d_in[8];  const float* ca_bq = (const float*)d_in[9];
    const float* ca_wk = (const float*)d_in[10]; const float* ca_bk = (const float*)d_in[11];
    const float* ca_wv = (const float*)d_in[12]; const float* ca_bv = (const float*)d_in[13];
    const float* ff_w1 = (const float*)d_in[14]; const float* ff_b1 = (const float*)d_in[15];
    const float* ff_w2 = (const float*)d_in[16]; const float* ff_b2 = (const float*)d_in[17];
    float* out = (float*)d_out;

    cudaFuncSetAttribute(attn_kernel, cudaFuncAttributeMaxDynamicSharedMemorySize, ATTN_SMEM);

    cudaMemcpyAsync(out, x, sizeof(float) * Bn * Tn * Cn, cudaMemcpyDeviceToDevice);

    const size_t WS = (size_t)Hn * Cn * DHn;
    const size_t BS = (size_t)Hn * DHn;

    for (int l = 0; l < Ln; l++) {
        // ---- self attention ----
        qkv_proj_kernel<<<dim3(Bn * Hn, 3), 256>>>(out, out,
            sa_wq + l * WS, sa_bq + l * BS,
            sa_wk + l * WS, sa_bk + l * BS,
            sa_wv + l * WS, sa_bv + l * BS);
        attn_kernel<<<Bn * Hn, 256, ATTN_SMEM>>>();
        add_ln_kernel<<<Bn, 1024>>>(out);

        // ---- cross attention ----
        qkv_proj_kernel<<<dim3(Bn * Hn, 3), 256>>>(out, enc,
            ca_wq + l * WS, ca_bq + l * BS,
            ca_wk + l * WS, ca_bk + l * BS,
            ca_wv + l * WS, ca_bv + l * BS);
        attn_kernel<<<Bn * Hn, 256, ATTN_SMEM>>>();
        add_ln_kernel<<<Bn, 1024>>>(out);

        // ---- feed forward ----
        gemm_tf32_kernel<0><<<dim3(FFn / 128, (Bn * Tn) / 128), 256>>>(
            out, ff_w1 + (size_t)l * Cn * FFn, ff_b1 + (size_t)l * FFn,
            Bn * Tn, FFn, Cn);
        gemm_tf32_kernel<1><<<dim3(Cn / 128, (Bn * Tn) / 128), 256>>>(
            nullptr, ff_w2 + (size_t)l * FFn * Cn, ff_b2 + (size_t)l * Cn,
            Bn * Tn, Cn, FFn);
        add_ln_kernel<<<Bn, 1024>>>(out);
    }
}

// round 4
// speedup vs baseline: 4.0561x; 1.6090x over previous
#include <cuda_runtime.h>

#define Bn 64
#define Tn 128
#define Sn 128
#define Cn 512
#define Hn 8
#define DHn 64
#define FFn 2048
#define Ln 6

// ---------------- scratch (device globals; no allocation allowed) ----------------
__device__ float g_q[Bn*Tn*Cn];          // [B*T, H*DH] head-concat layout
__device__ float g_k[Bn*Sn*Cn];
__device__ float g_v[Bn*Sn*Cn];
__device__ float g_attn[Bn*Tn*Cn];       // attention / FF2 output (residual source)
__device__ float g_h[(size_t)Bn*Tn*FFn]; // FF hidden (tf32-rounded)
__device__ float g_xt[Bn*Tn*Cn];         // tf32 mirror of x
__device__ float g_enct[Bn*Sn*Cn];       // tf32 mirror of encoder output
__device__ float g_wsaq[Ln*Cn*Cn], g_wsak[Ln*Cn*Cn], g_wsav[Ln*Cn*Cn];
__device__ float g_wcaq[Ln*Cn*Cn], g_wcak[Ln*Cn*Cn], g_wcav[Ln*Cn*Cn];
__device__ float g_wff1[(size_t)Ln*Cn*FFn];
__device__ float g_wff2[(size_t)Ln*FFn*Cn];

// ---------------- tf32 helpers ----------------
__device__ __forceinline__ unsigned f2tf(float f) {
    unsigned u;
    asm("cvt.rna.tf32.f32 %0, %1;" : "=r"(u) : "f"(f));
    return u;
}
__device__ __forceinline__ void mma8(float c[4], const unsigned a[4], const unsigned b[2]) {
    asm volatile("mma.sync.aligned.m16n8k8.row.col.f32.tf32.tf32.f32 "
        "{%0,%1,%2,%3}, {%4,%5,%6,%7}, {%8,%9}, {%0,%1,%2,%3};"
        : "+f"(c[0]), "+f"(c[1]), "+f"(c[2]), "+f"(c[3])
        : "r"(a[0]), "r"(a[1]), "r"(a[2]), "r"(a[3]), "r"(b[0]), "r"(b[1]));
}
__device__ __forceinline__ void cpasync16(void* s, const void* g) {
    unsigned sa = (unsigned)__cvta_generic_to_shared(s);
    asm volatile("cp.async.cg.shared.global [%0], [%1], 16;" :: "r"(sa), "l"(g));
}

// ---------------- conversion kernels (run once per launch) ----------------
__global__ void cvt_kernel(const float* __restrict__ src, float* __restrict__ dst, int n) {
    int i = blockIdx.x * 256 + threadIdx.x;
    if (i < n) dst[i] = __uint_as_float(f2tf(src[i]));
}
// src [L,H,C,DH] -> dst [L,C,H*DH] with tf32 rounding
__global__ void cvt_qkvw_kernel(const float* __restrict__ src, float* __restrict__ dst) {
    int i = blockIdx.x * 256 + threadIdx.x;  // < L*H*C*DH
    int d = i & 63, c = (i >> 6) & 511, h = (i >> 15) & 7, l = i >> 18;
    dst[((size_t)(l * Cn + c)) * 512 + h * 64 + d] = __uint_as_float(f2tf(src[i]));
}

// ---------------- unified tf32 GEMM core: 128x128 tile, cp.async double buffer --------
#define ASTR 36
#define BSTR 136
#define ABUF (128*ASTR)
#define BBUF (32*BSTR)
#define GEMM_SMEM ((2*ABUF + 2*BBUF) * (int)sizeof(float))   // 71680 B

__device__ __forceinline__ void gemm_core(
    const float* __restrict__ A, const float* __restrict__ W,
    const float* __restrict__ bias, float* __restrict__ outp,
    int N, int K, int rowTile, int colTile, bool relu, bool cvtOut, float* smem)
{
    float* As = smem;
    float* Bs = smem + 2 * ABUF;

    int tid = threadIdx.x, wid = tid >> 5, lane = tid & 31;
    int wm = wid >> 2, wn = wid & 3, g = lane >> 2, t = lane & 3;

    float acc[4][4][4];
    #pragma unroll
    for (int i = 0; i < 4; i++)
        #pragma unroll
        for (int j = 0; j < 4; j++)
            #pragma unroll
            for (int q = 0; q < 4; q++) acc[i][j][q] = 0.f;

    const float* Ab = A + (size_t)rowTile * K;
    const float* Wb = W + colTile;
    int KT = K >> 5;

    #pragma unroll
    for (int j = 0; j < 4; j++) {
        int q = tid + j * 256; int r = q >> 3, ko = (q & 7) * 4;
        cpasync16(&As[r * ASTR + ko], &Ab[(size_t)r * K + ko]);
    }
    #pragma unroll
    for (int j = 0; j < 4; j++) {
        int q = tid + j * 256; int kk = q >> 5, no = (q & 31) * 4;
        cpasync16(&Bs[kk * BSTR + no], &Wb[(size_t)kk * N + no]);
    }
    asm volatile("cp.async.commit_group;");

    for (int kt = 0; kt < KT; kt++) {
        if (kt + 1 < KT) {
            int k0 = (kt + 1) << 5;
            float* Ad = As + ((kt + 1) & 1) * ABUF;
            float* Bd = Bs + ((kt + 1) & 1) * BBUF;
            #pragma unroll
            for (int j = 0; j < 4; j++) {
                int q = tid + j * 256; int r = q >> 3, ko = (q & 7) * 4;
                cpasync16(&Ad[r * ASTR + ko], &Ab[(size_t)r * K + k0 + ko]);
            }
            #pragma unroll
            for (int j = 0; j < 4; j++) {
                int q = tid + j * 256; int kk = q >> 5, no = (q & 31) * 4;
                cpasync16(&Bd[kk * BSTR + no], &Wb[(size_t)(k0 + kk) * N + no]);
            }
            asm volatile("cp.async.commit_group;");
            asm volatile("cp.async.wait_group 1;");
        } else {
            asm volatile("cp.async.wait_group 0;");
        }
        __syncthreads();

        const unsigned* Au = (const unsigned*)(As + (kt & 1) * ABUF);
        const unsigned* Bu = (const unsigned*)(Bs + (kt & 1) * BBUF);
        #pragma unroll
        for (int ks = 0; ks < 4; ks++) {
            int c = ks * 8 + t;
            unsigned a[4][4], bf[4][2];
            #pragma unroll
            for (int i = 0; i < 4; i++) {
                int r = wm * 64 + i * 16 + g;
                a[i][0] = Au[r * ASTR + c];
                a[i][1] = Au[(r + 8) * ASTR + c];
                a[i][2] = Au[r * ASTR + c + 4];
                a[i][3] = Au[(r + 8) * ASTR + c + 4];
            }
            #pragma unroll
            for (int j = 0; j < 4; j++) {
                int n = wn * 32 + j * 8 + g;
                bf[j][0] = Bu[c * BSTR + n];
                bf[j][1] = Bu[(c + 4) * BSTR + n];
            }
            #pragma unroll
            for (int i = 0; i < 4; i++)
                #pragma unroll
                for (int j = 0; j < 4; j++)
                    mma8(acc[i][j], a[i], bf[j]);
        }
        __syncthreads();
    }

    #pragma unroll
    for (int i = 0; i < 4; i++) {
        int r0 = rowTile + wm * 64 + i * 16 + g;
        #pragma unroll
        for (int j = 0; j < 4; j++) {
            int c = colTile + wn * 32 + j * 8 + 2 * t;
            float b0 = bias[c], b1 = bias[c + 1];
            float v0 = acc[i][j][0] + b0, v1 = acc[i][j][1] + b1;
            float v2 = acc[i][j][2] + b0, v3 = acc[i][j][3] + b1;
            if (relu) {
                v0 = fmaxf(v0, 0.f); v1 = fmaxf(v1, 0.f);
                v2 = fmaxf(v2, 0.f); v3 = fmaxf(v3, 0.f);
            }
            if (cvtOut) {
                v0 = __uint_as_float(f2tf(v0)); v1 = __uint_as_float(f2tf(v1));
                v2 = __uint_as_float(f2tf(v2)); v3 = __uint_as_float(f2tf(v3));
            }
            *(float2*)&outp[(size_t)r0 * N + c]       = make_float2(v0, v1);
            *(float2*)&outp[(size_t)(r0 + 8) * N + c] = make_float2(v2, v3);
        }
    }
}

__global__ __launch_bounds__(256, 2) void gemm_qkv_kernel(
    const float* __restrict__ Aq, const float* __restrict__ Akv,
    const float* __restrict__ wq, const float* __restrict__ wk, const float* __restrict__ wv,
    const float* __restrict__ bq, const float* __restrict__ bk, const float* __restrict__ bv)
{
    extern __shared__ float smem[];
    const float* A; const float* W; const float* bias; float* outp;
    int z = blockIdx.z;
    if (z == 0)      { A = Aq;  W = wq; bias = bq; outp = g_q; }
    else if (z == 1) { A = Akv; W = wk; bias = bk; outp = g_k; }
    else             { A = Akv; W = wv; bias = bv; outp = g_v; }
    gemm_core(A, W, bias, outp, 512, 512, blockIdx.y * 128, blockIdx.x * 128,
              false, false, smem);
}

// FF1: A=g_xt -> g_h (relu + tf32 round). FF2: A=g_h -> g_attn.
__global__ __launch_bounds__(256, 2) void gemm_ff1_kernel(
    const float* __restrict__ A, const float* __restrict__ W,
    const float* __restrict__ bias)
{
    extern __shared__ float smem[];
    gemm_core(A, W, bias, g_h, FFn, Cn, blockIdx.y * 128, blockIdx.x * 128,
              true, true, smem);
}
__global__ __launch_bounds__(256, 2) void gemm_ff2_kernel(
    const float* __restrict__ W, const float* __restrict__ bias)
{
    extern __shared__ float smem[];
    gemm_core(g_h, W, bias, g_attn, Cn, FFn, blockIdx.y * 128, blockIdx.x * 128,
              false, false, smem);
}

// ---------------- fused attention per (b,h): softmax(QK^T/8)V with tf32 mma -----------
#define QS 68
#define PS 132
#define ATTN_SMEM ((3*128*QS + 128*PS) * (int)sizeof(float))   // 172032 B

__global__ __launch_bounds__(256) void attn_kernel()
{
    extern __shared__ float sm[];
    float* Qs = sm;
    float* Ks = sm + 128*QS;
    float* Vs = sm + 2*128*QS;
    float* Ps = sm + 3*128*QS;

    int bh = blockIdx.x;
    int h = bh & (Hn - 1);
    int b = bh >> 3;
    int tid = threadIdx.x, wid = tid >> 5, lane = tid & 31;
    int g = lane >> 2, t = lane & 3;

    const float* qg = g_q + (size_t)b * Tn * Cn + h * DHn;
    const float* kg = g_k + (size_t)b * Sn * Cn + h * DHn;
    const float* vg = g_v + (size_t)b * Sn * Cn + h * DHn;

    for (int e = tid; e < Tn * DHn; e += 256) {
        int r = e >> 6, d = e & 63;
        Qs[r*QS + d] = __uint_as_float(f2tf(qg[(size_t)r * Cn + d] * 0.125f));
        Ks[r*QS + d] = __uint_as_float(f2tf(kg[(size_t)r * Cn + d]));
        Vs[r*QS + d] = __uint_as_float(f2tf(vg[(size_t)r * Cn + d]));
    }
    __syncthreads();

    {
        int wm = wid >> 2, wn = wid & 3;
        float acc[4][4][4];
        #pragma unroll
        for (int i = 0; i < 4; i++)
            #pragma unroll
            for (int j = 0; j < 4; j++)
                #pragma unroll
                for (int q = 0; q < 4; q++) acc[i][j][q] = 0.f;

        const unsigned* Qu = (const unsigned*)Qs;
        const unsigned* Ku = (const unsigned*)Ks;
        #pragma unroll
        for (int ks = 0; ks < 8; ks++) {
            int c = ks*8 + t;
            unsigned a[4][4], bf[4][2];
            #pragma unroll
            for (int i = 0; i < 4; i++) {
                int r = wm*64 + i*16 + g;
                a[i][0] = Qu[r*QS + c];
                a[i][1] = Qu[(r+8)*QS + c];
                a[i][2] = Qu[r*QS + c + 4];
                a[i][3] = Qu[(r+8)*QS + c + 4];
            }
            #pragma unroll
            for (int j = 0; j < 4; j++) {
                int n = wn*32 + j*8 + g;
                bf[j][0] = Ku[n*QS + c];
                bf[j][1] = Ku[n*QS + c + 4];
            }
            #pragma unroll
            for (int i = 0; i < 4; i++)
                #pragma unroll
                for (int j = 0; j < 4; j++)
                    mma8(acc[i][j], a[i], bf[j]);
        }
        #pragma unroll
        for (int i = 0; i < 4; i++) {
            int r0 = wm*64 + i*16 + g;
            #pragma unroll
            for (int j = 0; j < 4; j++) {
                int c = wn*32 + j*8 + 2*t;
                *(float2*)&Ps[r0*PS + c]     = make_float2(acc[i][j][0], acc[i][j][1]);
                *(float2*)&Ps[(r0+8)*PS + c] = make_float2(acc[i][j][2], acc[i][j][3]);
            }
        }
    }
    __syncthreads();

    {
        int row = tid >> 1;
        float* p = Ps + row*PS + (tid & 1) * 64;
        float mx = -1e30f;
        #pragma unroll 8
        for (int j = 0; j < 64; j++) mx = fmaxf(mx, p[j]);
        mx = fmaxf(mx, __shfl_xor_sync(0xffffffffu, mx, 1));
        float s = 0.f;
        #pragma unroll 8
        for (int j = 0; j < 64; j++) { float e = __expf(p[j] - mx); p[j] = e; s += e; }
        s += __shfl_xor_sync(0xffffffffu, s, 1);
        float inv = 1.f / s;
        #pragma unroll 8
        for (int j = 0; j < 64; j++) p[j] = __uint_as_float(f2tf(p[j] * inv));
    }
    __syncthreads();

    {
        int wm = wid >> 1, wn = wid & 1;
        float acc[2][4][4];
        #pragma unroll
        for (int i = 0; i < 2; i++)
            #pragma unroll
            for (int j = 0; j < 4; j++)
                #pragma unroll
                for (int q = 0; q < 4; q++) acc[i][j][q] = 0.f;

        const unsigned* Pu = (const unsigned*)Ps;
        const unsigned* Vu = (const unsigned*)Vs;
        #pragma unroll
        for (int ks = 0; ks < 16; ks++) {
            int c = ks*8 + t;
            unsigned a[2][4], bf[4][2];
            #pragma unroll
            for (int i = 0; i < 2; i++) {
                int r = wm*32 + i*16 + g;
                a[i][0] = Pu[r*PS + c];
                a[i][1] = Pu[(r+8)*PS + c];
                a[i][2] = Pu[r*PS + c + 4];
                a[i][3] = Pu[(r+8)*PS + c + 4];
            }
            #pragma unroll
            for (int j = 0; j < 4; j++) {
                int n = wn*32 + j*8 + g;
                bf[j][0] = Vu[c*QS + n];
                bf[j][1] = Vu[(c+4)*QS + n];
            }
            #pragma unroll
            for (int i = 0; i < 2; i++)
                #pragma unroll
                for (int j = 0; j < 4; j++)
                    mma8(acc[i][j], a[i], bf[j]);
        }

        float* og = g_attn + (size_t)b * Tn * Cn + (size_t)h * DHn;
        #pragma unroll
        for (int i = 0; i < 2; i++) {
            int r0 = wm*32 + i*16 + g;
            #pragma unroll
            for (int j = 0; j < 4; j++) {
                int c = wn*32 + j*8 + 2*t;
                *(float2*)&og[(size_t)r0*Cn + c]     = make_float2(acc[i][j][0], acc[i][j][1]);
                *(float2*)&og[(size_t)(r0+8)*Cn + c] = make_float2(acc[i][j][2], acc[i][j][3]);
            }
        }
    }
}

// -------- residual add + joint (T,C) LayerNorm; writes fp32 x and tf32 mirror ---------
__global__ __launch_bounds__(1024) void add_ln_kernel(float* __restrict__ x)
{
    int b = blockIdx.x;
    float4* x4 = (float4*)(x + (size_t)b * Tn * Cn);
    float4* xt4 = (float4*)(g_xt + (size_t)b * Tn * Cn);
    const float4* r4 = (const float4*)(g_attn + (size_t)b * Tn * Cn);
    int tid = threadIdx.x, lane = tid & 31, wid = tid >> 5;
    const int N4 = Tn * Cn / 4;

    float s = 0.f, s2 = 0.f;
    for (int i = tid; i < N4; i += 1024) {
        float4 a = x4[i], r = r4[i];
        a.x += r.x; a.y += r.y; a.z += r.z; a.w += r.w;
        x4[i] = a;
        s  += a.x + a.y + a.z + a.w;
        s2 += a.x*a.x + a.y*a.y + a.z*a.z + a.w*a.w;
    }
    #pragma unroll
    for (int o = 16; o > 0; o >>= 1) {
        s  += __shfl_xor_sync(0xffffffffu, s, o);
        s2 += __shfl_xor_sync(0xffffffffu, s2, o);
    }
    __shared__ float sa[32], sb[32], stat[2];
    if (lane == 0) { sa[wid] = s; sb[wid] = s2; }
    __syncthreads();
    if (tid < 32) {
        s = sa[tid]; s2 = sb[tid];
        #pragma unroll
        for (int o = 16; o > 0; o >>= 1) {
            s  += __shfl_xor_sync(0xffffffffu, s, o);
            s2 += __shfl_xor_sync(0xffffffffu, s2, o);
        }
        if (tid == 0) {
            const float invN = 1.f / (Tn * Cn);
            float mu  = s * invN;
            float var = s2 * invN - mu * mu;
            stat[0] = mu;
            stat[1] = rsqrtf(var + 1e-5f);
        }
    }
    __syncthreads();
    float mu = stat[0], inv = stat[1];
    for (int i = tid; i < N4; i += 1024) {
        float4 a = x4[i];
        a.x = (a.x - mu) * inv; a.y = (a.y - mu) * inv;
        a.z = (a.z - mu) * inv; a.w = (a.w - mu) * inv;
        x4[i] = a;
        float4 tcv;
        tcv.x = __uint_as_float(f2tf(a.x)); tcv.y = __uint_as_float(f2tf(a.y));
        tcv.z = __uint_as_float(f2tf(a.z)); tcv.w = __uint_as_float(f2tf(a.w));
        xt4[i] = tcv;
    }
}

// ---------------- driver ----------------
extern "C" void kernel_launch(void* const* d_in, const int* in_sizes, int n_in,
                              void* d_out, int out_size)
{
    const float* x     = (const float*)d_in[0];
    const float* enc   = (const float*)d_in[1];
    const float* sa_wq = (const float*)d_in[2];  const float* sa_bq = (const float*)d_in[3];
    const float* sa_wk = (const float*)d_in[4];  const float* sa_bk = (const float*)d_in[5];
    const float* sa_wv = (const float*)d_in[6];  const float* sa_bv = (const float*)d_in[7];
    const float* ca_wq = (const float*)d_in[8];  const float* ca_bq = (const float*)d_in[9];
    const float* ca_wk = (const float*)d_in[10]; const float* ca_bk = (const float*)d_in[11];
    const float* ca_wv = (const float*)d_in[12]; const float* ca_bv = (const float*)d_in[13];
    const float* ff_w1 = (const float*)d_in[14]; const float* ff_b1 = (const float*)d_in[15];
    const float* ff_w2 = (const float*)d_in[16]; const float* ff_b2 = (const float*)d_in[17];
    float* out = (float*)d_out;

    cudaFuncSetAttribute(attn_kernel, cudaFuncAttributeMaxDynamicSharedMemorySize, ATTN_SMEM);
    cudaFuncSetAttribute(gemm_qkv_kernel, cudaFuncAttributeMaxDynamicSharedMemorySize, GEMM_SMEM);
    cudaFuncSetAttribute(gemm_ff1_kernel, cudaFuncAttributeMaxDynamicSharedMemorySize, GEMM_SMEM);
    cudaFuncSetAttribute(gemm_ff2_kernel, cudaFuncAttributeMaxDynamicSharedMemorySize, GEMM_SMEM);

    float *wsaq, *wsak, *wsav, *wcaq, *wcak, *wcav, *wff1, *wff2, *xt, *enct;
    cudaGetSymbolAddress((void**)&wsaq, g_wsaq);
    cudaGetSymbolAddress((void**)&wsak, g_wsak);
    cudaGetSymbolAddress((void**)&wsav, g_wsav);
    cudaGetSymbolAddress((void**)&wcaq, g_wcaq);
    cudaGetSymbolAddress((void**)&wcak, g_wcak);
    cudaGetSymbolAddress((void**)&wcav, g_wcav);
    cudaGetSymbolAddress((void**)&wff1, g_wff1);
    cudaGetSymbolAddress((void**)&wff2, g_wff2);
    cudaGetSymbolAddress((void**)&xt,   g_xt);
    cudaGetSymbolAddress((void**)&enct, g_enct);

    cudaMemcpyAsync(out, x, sizeof(float) * Bn * Tn * Cn, cudaMemcpyDeviceToDevice);

    const int nAct = Bn * Tn * Cn;
    cvt_kernel<<<(nAct + 255) / 256, 256>>>(x, xt, nAct);
    cvt_kernel<<<(nAct + 255) / 256, 256>>>(enc, enct, nAct);
    const int nQW = Ln * Hn * Cn * DHn;
    cvt_qkvw_kernel<<<nQW / 256, 256>>>(sa_wq, wsaq);
    cvt_qkvw_kernel<<<nQW / 256, 256>>>(sa_wk, wsak);
    cvt_qkvw_kernel<<<nQW / 256, 256>>>(sa_wv, wsav);
    cvt_qkvw_kernel<<<nQW / 256, 256>>>(ca_wq, wcaq);
    cvt_qkvw_kernel<<<nQW / 256, 256>>>(ca_wk, wcak);
    cvt_qkvw_kernel<<<nQW / 256, 256>>>(ca_wv, wcav);
    const int nFW = Ln * Cn * FFn;
    cvt_kernel<<<(nFW + 255) / 256, 256>>>(ff_w1, wff1, nFW);
    cvt_kernel<<<(nFW + 255) / 256, 256>>>(ff_w2, wff2, nFW);

    const size_t WSTRIDE = (size_t)Cn * 512;
    const size_t BSTRIDE = (size_t)Hn * DHn;

    for (int l = 0; l < Ln; l++) {
        gemm_qkv_kernel<<<dim3(4, 64, 3), 256, GEMM_SMEM>>>(xt, xt,
            wsaq + l * WSTRIDE, wsak + l * WSTRIDE, wsav + l * WSTRIDE,
            sa_bq + l * BSTRIDE, sa_bk + l * BSTRIDE, sa_bv + l * BSTRIDE);
        attn_kernel<<<Bn * Hn, 256, ATTN_SMEM>>>();
        add_ln_kernel<<<Bn, 1024>>>(out);

        gemm_qkv_kernel<<<dim3(4, 64, 3), 256, GEMM_SMEM>>>(xt, enct,
            wcaq + l * WSTRIDE, wcak + l * WSTRIDE, wcav + l * WSTRIDE,
            ca_bq + l * BSTRIDE, ca_bk + l * BSTRIDE, ca_bv + l * BSTRIDE);
        attn_kernel<<<Bn * Hn, 256, ATTN_SMEM>>>();
        add_ln_kernel<<<Bn, 1024>>>(out);

        gemm_ff1_kernel<<<dim3(FFn / 128, (Bn * Tn) / 128), 256, GEMM_SMEM>>>(
            xt, wff1 + (size_t)l * Cn * FFn, ff_b1 + (size_t)l * FFn);
        gemm_ff2_kernel<<<dim3(Cn / 128, (Bn * Tn) / 128), 256, GEMM_SMEM>>>(
            wff2 + (size_t)l * FFn * Cn, ff_b2 + (size_t)l * Cn);
        add_ln_kernel<<<Bn, 1024>>>(out);
    }
}

// round 6
// speedup vs baseline: 4.6666x; 1.1505x over previous
#include <cuda_runtime.h>

#define Bn 64
#define Tn 128
#define Sn 128
#define Cn 512
#define Hn 8
#define DHn 64
#define FFn 2048
#define Ln 6

// ---------------- scratch (device globals; no allocation allowed) ----------------
__device__ float g_q[Bn*Tn*Cn];          // [B*T, H*DH]
__device__ float g_k[Bn*Sn*Cn];
__device__ float g_v[Bn*Sn*Cn];
__device__ float g_y[Bn*Tn*Cn];          // pre-norm y = x + residual
__device__ float g_h[(size_t)Bn*Tn*FFn]; // FF hidden (tf32-rounded)
__device__ float g_xt[Bn*Tn*Cn];         // tf32 mirror of x
__device__ float g_enct[Bn*Sn*Cn];       // tf32 mirror of encoder output
__device__ float g_ps[Bn*8], g_ps2[Bn*8];// LN partial stats (slots)
__device__ float g_wsaq[Ln*Cn*Cn], g_wsak[Ln*Cn*Cn], g_wsav[Ln*Cn*Cn];
__device__ float g_wcaq[Ln*Cn*Cn], g_wcak[Ln*Cn*Cn], g_wcav[Ln*Cn*Cn];
__device__ float g_wff1[(size_t)Ln*Cn*FFn];
__device__ float g_wff2[(size_t)Ln*FFn*Cn];

// ---------------- tf32 helpers ----------------
__device__ __forceinline__ unsigned f2tf(float f) {
    unsigned u;
    asm("cvt.rna.tf32.f32 %0, %1;" : "=r"(u) : "f"(f));
    return u;
}
__device__ __forceinline__ float f2tff(float f) { return __uint_as_float(f2tf(f)); }
__device__ __forceinline__ void mma8(float c[4], const unsigned a[4], const unsigned b[2]) {
    asm volatile("mma.sync.aligned.m16n8k8.row.col.f32.tf32.tf32.f32 "
        "{%0,%1,%2,%3}, {%4,%5,%6,%7}, {%8,%9}, {%0,%1,%2,%3};"
        : "+f"(c[0]), "+f"(c[1]), "+f"(c[2]), "+f"(c[3])
        : "r"(a[0]), "r"(a[1]), "r"(a[2]), "r"(a[3]), "r"(b[0]), "r"(b[1]));
}
__device__ __forceinline__ void cpasync16(void* s, const void* g) {
    unsigned sa = (unsigned)__cvta_generic_to_shared(s);
    asm volatile("cp.async.cg.shared.global [%0], [%1], 16;" :: "r"(sa), "l"(g));
}

// ---------------- conversion kernels (once per launch) ----------------
__global__ void cvt_kernel(const float* __restrict__ src, float* __restrict__ dst, int n) {
    int i = blockIdx.x * 256 + threadIdx.x;
    if (i < n) dst[i] = f2tff(src[i]);
}
// src [L,H,C,DH] -> dst [L,C,H*DH] with tf32 rounding
__global__ void cvt_qkvw_kernel(const float* __restrict__ src, float* __restrict__ dst) {
    int i = blockIdx.x * 256 + threadIdx.x;
    int d = i & 63, c = (i >> 6) & 511, h = (i >> 15) & 7, l = i >> 18;
    dst[((size_t)(l * Cn + c)) * 512 + h * 64 + d] = f2tff(src[i]);
}

// ---------------- unified tf32 GEMM core: 128x128 tile, 3-stage cp.async --------------
#define ASTR 36
#define BSTR 136
#define ABUF (128*ASTR)
#define BBUF (32*BSTR)
#define NSTG 3
#define GEMM_SMEM ((NSTG*ABUF + NSTG*BBUF) * (int)sizeof(float))   // 107520 B

// EPI: 0 = bias only, 1 = relu + tf32 round, 2 = residual add + LN partial stats
template<int EPI>
__device__ __forceinline__ void gemm_core(
    const float* __restrict__ A, const float* __restrict__ W,
    const float* __restrict__ bias, float* __restrict__ outp,
    const float* __restrict__ resid,
    int N, int K, int rowTile, int colTile, float* smem)
{
    float* As = smem;
    float* Bs = smem + NSTG * ABUF;

    int tid = threadIdx.x, wid = tid >> 5, lane = tid & 31;
    int wm = wid >> 2, wn = wid & 3, g = lane >> 2, t = lane & 3;

    float acc[4][4][4];
    #pragma unroll
    for (int i = 0; i < 4; i++)
        #pragma unroll
        for (int j = 0; j < 4; j++)
            #pragma unroll
            for (int q = 0; q < 4; q++) acc[i][j][q] = 0.f;

    const float* Ab = A + (size_t)rowTile * K;
    const float* Wb = W + colTile;
    int KT = K >> 5;

    // prologue: stage slabs 0, 1
    #pragma unroll
    for (int st = 0; st < 2; st++) {
        int k0 = st << 5;
        float* Ad = As + st * ABUF;
        float* Bd = Bs + st * BBUF;
        #pragma unroll
        for (int j = 0; j < 4; j++) {
            int q = tid + j * 256; int r = q >> 3, ko = (q & 7) * 4;
            cpasync16(&Ad[r * ASTR + ko], &Ab[(size_t)r * K + k0 + ko]);
        }
        #pragma unroll
        for (int j = 0; j < 4; j++) {
            int q = tid + j * 256; int kk = q >> 5, no = (q & 31) * 4;
            cpasync16(&Bd[kk * BSTR + no], &Wb[(size_t)(k0 + kk) * N + no]);
        }
        asm volatile("cp.async.commit_group;");
    }

    int buf = 0;
    for (int kt = 0; kt < KT; kt++) {
        asm volatile("cp.async.wait_group 1;");
        __syncthreads();

        const unsigned* Au = (const unsigned*)(As + buf * ABUF);
        const unsigned* Bu = (const unsigned*)(Bs + buf * BBUF);
        #pragma unroll
        for (int ks = 0; ks < 4; ks++) {
            int c = ks * 8 + t;
            unsigned a[4][4], bf[4][2];
            #pragma unroll
            for (int i = 0; i < 4; i++) {
                int r = wm * 64 + i * 16 + g;
                a[i][0] = Au[r * ASTR + c];
                a[i][1] = Au[(r + 8) * ASTR + c];
                a[i][2] = Au[r * ASTR + c + 4];
                a[i][3] = Au[(r + 8) * ASTR + c + 4];
            }
            #pragma unroll
            for (int j = 0; j < 4; j++) {
                int n = wn * 32 + j * 8 + g;
                bf[j][0] = Bu[c * BSTR + n];
                bf[j][1] = Bu[(c + 4) * BSTR + n];
            }
            #pragma unroll
            for (int i = 0; i < 4; i++)
                #pragma unroll
                for (int j = 0; j < 4; j++)
                    mma8(acc[i][j], a[i], bf[j]);
        }

        // prefetch slab kt+2 into the third buffer (safe: all warps passed the
        // sync above, so mma on that buffer from iteration kt-1 is complete)
        if (kt + 2 < KT) {
            int k0 = (kt + 2) << 5;
            int nb = kt + 2; nb -= (nb / NSTG) * NSTG;
            float* Ad = As + nb * ABUF;
            float* Bd = Bs + nb * BBUF;
            #pragma unroll
            for (int j = 0; j < 4; j++) {
                int q = tid + j * 256; int r = q >> 3, ko = (q & 7) * 4;
                cpasync16(&Ad[r * ASTR + ko], &Ab[(size_t)r * K + k0 + ko]);
            }
            #pragma unroll
            for (int j = 0; j < 4; j++) {
                int q = tid + j * 256; int kk = q >> 5, no = (q & 31) * 4;
                cpasync16(&Bd[kk * BSTR + no], &Wb[(size_t)(k0 + kk) * N + no]);
            }
        }
        asm volatile("cp.async.commit_group;");   // commit (possibly empty) to keep counts aligned

        buf++; if (buf == NSTG) buf = 0;
    }

    float s = 0.f, s2 = 0.f;
    #pragma unroll
    for (int i = 0; i < 4; i++) {
        int r0 = rowTile + wm * 64 + i * 16 + g;
        #pragma unroll
        for (int j = 0; j < 4; j++) {
            int c = colTile + wn * 32 + j * 8 + 2 * t;
            float b0 = bias[c], b1 = bias[c + 1];
            float v0 = acc[i][j][0] + b0, v1 = acc[i][j][1] + b1;
            float v2 = acc[i][j][2] + b0, v3 = acc[i][j][3] + b1;
            if (EPI == 1) {
                v0 = f2tff(fmaxf(v0, 0.f)); v1 = f2tff(fmaxf(v1, 0.f));
                v2 = f2tff(fmaxf(v2, 0.f)); v3 = f2tff(fmaxf(v3, 0.f));
            }
            if (EPI == 2) {
                float2 x0 = *(const float2*)&resid[(size_t)r0 * N + c];
                float2 x1 = *(const float2*)&resid[(size_t)(r0 + 8) * N + c];
                v0 += x0.x; v1 += x0.y; v2 += x1.x; v3 += x1.y;
                s  += v0 + v1 + v2 + v3;
                s2 += v0*v0 + v1*v1 + v2*v2 + v3*v3;
            }
            *(float2*)&outp[(size_t)r0 * N + c]       = make_float2(v0, v1);
            *(float2*)&outp[(size_t)(r0 + 8) * N + c] = make_float2(v2, v3);
        }
    }

    if (EPI == 2) {
        __shared__ float rs[8], rs2[8];
        #pragma unroll
        for (int o = 16; o > 0; o >>= 1) {
            s  += __shfl_xor_sync(0xffffffffu, s, o);
            s2 += __shfl_xor_sync(0xffffffffu, s2, o);
        }
        if (lane == 0) { rs[wid] = s; rs2[wid] = s2; }
        __syncthreads();
        if (tid == 0) {
            float ts = 0.f, ts2 = 0.f;
            #pragma unroll
            for (int i = 0; i < 8; i++) { ts += rs[i]; ts2 += rs2[i]; }
            int slot = (rowTile >> 7) * 8 + (colTile >> 7);
            g_ps[slot] = ts; g_ps2[slot] = ts2;
        }
    }
}

__global__ __launch_bounds__(256, 2) void gemm_qkv_kernel(
    const float* __restrict__ Aq, const float* __restrict__ Akv,
    const float* __restrict__ wq, const float* __restrict__ wk, const float* __restrict__ wv,
    const float* __restrict__ bq, const float* __restrict__ bk, const float* __restrict__ bv)
{
    extern __shared__ float smem[];
    const float* A; const float* W; const float* bias; float* outp;
    int z = blockIdx.z;
    if (z == 0)      { A = Aq;  W = wq; bias = bq; outp = g_q; }
    else if (z == 1) { A = Akv; W = wk; bias = bk; outp = g_k; }
    else             { A = Akv; W = wv; bias = bv; outp = g_v; }
    gemm_core<0>(A, W, bias, outp, nullptr, 512, 512,
                 blockIdx.y * 128, blockIdx.x * 128, smem);
}

__global__ __launch_bounds__(256, 2) void gemm_ff1_kernel(
    const float* __restrict__ A, const float* __restrict__ W,
    const float* __restrict__ bias)
{
    extern __shared__ float smem[];
    gemm_core<1>(A, W, bias, g_h, nullptr, FFn, Cn,
                 blockIdx.y * 128, blockIdx.x * 128, smem);
}
__global__ __launch_bounds__(256, 2) void gemm_ff2_kernel(
    const float* __restrict__ W, const float* __restrict__ bias,
    const float* __restrict__ resid)
{
    extern __shared__ float smem[];
    gemm_core<2>(g_h, W, bias, g_y, resid, Cn, FFn,
                 blockIdx.y * 128, blockIdx.x * 128, smem);
}

// ---------------- fused attention per (b,h) + residual add + LN partial stats --------
#define QS 68
#define PS 132
#define ATTN_SMEM ((3*128*QS + 128*PS) * (int)sizeof(float))   // 172032 B

__global__ __launch_bounds__(256) void attn_kernel(const float* __restrict__ resid)
{
    extern __shared__ float sm[];
    float* Qs = sm;
    float* Ks = sm + 128*QS;
    float* Vs = sm + 2*128*QS;
    float* Ps = sm + 3*128*QS;

    int bh = blockIdx.x;
    int h = bh & (Hn - 1);
    int b = bh >> 3;
    int tid = threadIdx.x, wid = tid >> 5, lane = tid & 31;
    int g = lane >> 2, t = lane & 3;

    const float* qg = g_q + (size_t)b * Tn * Cn + h * DHn;
    const float* kg = g_k + (size_t)b * Sn * Cn + h * DHn;
    const float* vg = g_v + (size_t)b * Sn * Cn + h * DHn;

    // float4 staging with tf32 rounding (Q pre-scaled by 1/8, exact in tf32)
    for (int e = tid; e < Tn * DHn / 4; e += 256) {
        int r = e >> 4, d = (e & 15) * 4;
        size_t gi = (size_t)r * Cn + d;
        float4 q = *(const float4*)&qg[gi];
        float4 k = *(const float4*)&kg[gi];
        float4 v = *(const float4*)&vg[gi];
        float* qd = &Qs[r*QS + d];
        qd[0] = f2tff(q.x * 0.125f); qd[1] = f2tff(q.y * 0.125f);
        qd[2] = f2tff(q.z * 0.125f); qd[3] = f2tff(q.w * 0.125f);
        float* kd = &Ks[r*QS + d];
        kd[0] = f2tff(k.x); kd[1] = f2tff(k.y); kd[2] = f2tff(k.z); kd[3] = f2tff(k.w);
        float* vd = &Vs[r*QS + d];
        vd[0] = f2tff(v.x); vd[1] = f2tff(v.y); vd[2] = f2tff(v.z); vd[3] = f2tff(v.w);
    }
    __syncthreads();

    // ---- scores = (Q/8) @ K^T : 128x128. warps 2(M)x4(N) ----
    {
        int wm = wid >> 2, wn = wid & 3;
        float acc[4][4][4];
        #pragma unroll
        for (int i = 0; i < 4; i++)
            #pragma unroll
            for (int j = 0; j < 4; j++)
                #pragma unroll
                for (int q = 0; q < 4; q++) acc[i][j][q] = 0.f;

        const unsigned* Qu = (const unsigned*)Qs;
        const unsigned* Ku = (const unsigned*)Ks;
        #pragma unroll
        for (int ks = 0; ks < 8; ks++) {
            int c = ks*8 + t;
            unsigned a[4][4], bf[4][2];
            #pragma unroll
            for (int i = 0; i < 4; i++) {
                int r = wm*64 + i*16 + g;
                a[i][0] = Qu[r*QS + c];
                a[i][1] = Qu[(r+8)*QS + c];
                a[i][2] = Qu[r*QS + c + 4];
                a[i][3] = Qu[(r+8)*QS + c + 4];
            }
            #pragma unroll
            for (int j = 0; j < 4; j++) {
                int n = wn*32 + j*8 + g;
                bf[j][0] = Ku[n*QS + c];
                bf[j][1] = Ku[n*QS + c + 4];
            }
            #pragma unroll
            for (int i = 0; i < 4; i++)
                #pragma unroll
                for (int j = 0; j < 4; j++)
                    mma8(acc[i][j], a[i], bf[j]);
        }
        #pragma unroll
        for (int i = 0; i < 4; i++) {
            int r0 = wm*64 + i*16 + g;
            #pragma unroll
            for (int j = 0; j < 4; j++) {
                int c = wn*32 + j*8 + 2*t;
                *(float2*)&Ps[r0*PS + c]     = make_float2(acc[i][j][0], acc[i][j][1]);
                *(float2*)&Ps[(r0+8)*PS + c] = make_float2(acc[i][j][2], acc[i][j][3]);
            }
        }
    }
    __syncthreads();

    // ---- softmax: 2 threads per row ----
    {
        int row = tid >> 1;
        float* p = Ps + row*PS + (tid & 1) * 64;
        float mx = -1e30f;
        #pragma unroll 8
        for (int j = 0; j < 64; j++) mx = fmaxf(mx, p[j]);
        mx = fmaxf(mx, __shfl_xor_sync(0xffffffffu, mx, 1));
        float s = 0.f;
        #pragma unroll 8
        for (int j = 0; j < 64; j++) { float e = __expf(p[j] - mx); p[j] = e; s += e; }
        s += __shfl_xor_sync(0xffffffffu, s, 1);
        float inv = 1.f / s;
        #pragma unroll 8
        for (int j = 0; j < 64; j++) p[j] = f2tff(p[j] * inv);
    }
    __syncthreads();

    // ---- O = P @ V, fused residual add + stats. warps 4(M)x2(N) ----
    {
        int wm = wid >> 1, wn = wid & 1;
        float acc[2][4][4];
        #pragma unroll
        for (int i = 0; i < 2; i++)
            #pragma unroll
            for (int j = 0; j < 4; j++)
                #pragma unroll
                for (int q = 0; q < 4; q++) acc[i][j][q] = 0.f;

        const unsigned* Pu = (const unsigned*)Ps;
        const unsigned* Vu = (const unsigned*)Vs;
        #pragma unroll
        for (int ks = 0; ks < 16; ks++) {
            int c = ks*8 + t;
            unsigned a[2][4], bf[4][2];
            #pragma unroll
            for (int i = 0; i < 2; i++) {
                int r = wm*32 + i*16 + g;
                a[i][0] = Pu[r*PS + c];
                a[i][1] = Pu[(r+8)*PS + c];
                a[i][2] = Pu[r*PS + c + 4];
                a[i][3] = Pu[(r+8)*PS + c + 4];
            }
            #pragma unroll
            for (int j = 0; j < 4; j++) {
                int n = wn*32 + j*8 + g;
                bf[j][0] = Vu[c*QS + n];
                bf[j][1] = Vu[(c+4)*QS + n];
            }
            #pragma unroll
            for (int i = 0; i < 2; i++)
                #pragma unroll
                for (int j = 0; j < 4; j++)
                    mma8(acc[i][j], a[i], bf[j]);
        }

        const float* xg = resid + (size_t)b * Tn * Cn + h * DHn;
        float* og = g_y + (size_t)b * Tn * Cn + (size_t)h * DHn;
        float s = 0.f, s2 = 0.f;
        #pragma unroll
        for (int i = 0; i < 2; i++) {
            int r0 = wm*32 + i*16 + g;
            #pragma unroll
            for (int j = 0; j < 4; j++) {
                int c = wn*32 + j*8 + 2*t;
                float2 x0 = *(const float2*)&xg[(size_t)r0*Cn + c];
                float2 x1 = *(const float2*)&xg[(size_t)(r0+8)*Cn + c];
                float v0 = acc[i][j][0] + x0.x, v1 = acc[i][j][1] + x0.y;
                float v2 = acc[i][j][2] + x1.x, v3 = acc[i][j][3] + x1.y;
                s  += v0 + v1 + v2 + v3;
                s2 += v0*v0 + v1*v1 + v2*v2 + v3*v3;
                *(float2*)&og[(size_t)r0*Cn + c]     = make_float2(v0, v1);
                *(float2*)&og[(size_t)(r0+8)*Cn + c] = make_float2(v2, v3);
            }
        }

        __shared__ float rs[8], rs2[8];
        #pragma unroll
        for (int o = 16; o > 0; o >>= 1) {
            s  += __shfl_xor_sync(0xffffffffu, s, o);
            s2 += __shfl_xor_sync(0xffffffffu, s2, o);
        }
        if (lane == 0) { rs[wid] = s; rs2[wid] = s2; }
        __syncthreads();
        if (tid == 0) {
            float ts = 0.f, ts2 = 0.f;
            #pragma unroll
            for (int i = 0; i < 8; i++) { ts += rs[i]; ts2 += rs2[i]; }
            g_ps[b*8 + h] = ts; g_ps2[b*8 + h] = ts2;
        }
    }
}

// ---------------- LN normalize: y -> x (fp32) + xt (tf32), wide grid -------------------
__global__ __launch_bounds__(256) void ln_norm_kernel(float* __restrict__ x, int nslots)
{
    int b = blockIdx.y, chunk = blockIdx.x;   // 8 chunks per batch
    float s = 0.f, s2 = 0.f;
    for (int i = 0; i < nslots; i++) { s += g_ps[b*8 + i]; s2 += g_ps2[b*8 + i]; }
    const float invN = 1.f / (Tn * Cn);
    float mu  = s * invN;
    float var = s2 * invN - mu * mu;
    float inv = rsqrtf(var + 1e-5f);

    size_t base4 = ((size_t)b * Tn * Cn + (size_t)chunk * (Tn * Cn / 8)) / 4;
    const float4* y4 = (const float4*)g_y + base4;
    float4* x4  = (float4*)x + base4;
    float4* xt4 = (float4*)g_xt + base4;
    const int n4 = Tn * Cn / 8 / 4;   // 2048
    int tid = threadIdx.x;
    for (int i = tid; i < n4; i += 256) {
        float4 a = y4[i];
        a.x = (a.x - mu) * inv; a.y = (a.y - mu) * inv;
        a.z = (a.z - mu) * inv; a.w = (a.w - mu) * inv;
        x4[i] = a;
        float4 tv;
        tv.x = f2tff(a.x); tv.y = f2tff(a.y); tv.z = f2tff(a.z); tv.w = f2tff(a.w);
        xt4[i] = tv;
    }
}

// ---------------- driver ----------------
extern "C" void kernel_launch(void* const* d_in, const int* in_sizes, int n_in,
                              void* d_out, int out_size)
{
    const float* x     = (const float*)d_in[0];
    const float* enc   = (const float*)d_in[1];
    const float* sa_wq = (const float*)d_in[2];  const float* sa_bq = (const float*)d_in[3];
    const float* sa_wk = (const float*)d_in[4];  const float* sa_bk = (const float*)d_in[5];
    const float* sa_wv = (const float*)d_in[6];  const float* sa_bv = (const float*)d_in[7];
    const float* ca_wq = (const float*)d_in[8];  const float* ca_bq = (const float*)d_in[9];
    const float* ca_wk = (const float*)d_in[10]; const float* ca_bk = (const float*)d_in[11];
    const float* ca_wv = (const float*)d_in[12]; const float* ca_bv = (const float*)d_in[13];
    const float* ff_w1 = (const float*)d_in[14]; const float* ff_b1 = (const float*)d_in[15];
    const float* ff_w2 = (const float*)d_in[16]; const float* ff_b2 = (const float*)d_in[17];
    float* out = (float*)d_out;

    cudaFuncSetAttribute(attn_kernel, cudaFuncAttributeMaxDynamicSharedMemorySize, ATTN_SMEM);
    cudaFuncSetAttribute(gemm_qkv_kernel, cudaFuncAttributeMaxDynamicSharedMemorySize, GEMM_SMEM);
    cudaFuncSetAttribute(gemm_ff1_kernel, cudaFuncAttributeMaxDynamicSharedMemorySize, GEMM_SMEM);
    cudaFuncSetAttribute(gemm_ff2_kernel, cudaFuncAttributeMaxDynamicSharedMemorySize, GEMM_SMEM);

    float *wsaq, *wsak, *wsav, *wcaq, *wcak, *wcav, *wff1, *wff2, *xt, *enct;
    cudaGetSymbolAddress((void**)&wsaq, g_wsaq);
    cudaGetSymbolAddress((void**)&wsak, g_wsak);
    cudaGetSymbolAddress((void**)&wsav, g_wsav);
    cudaGetSymbolAddress((void**)&wcaq, g_wcaq);
    cudaGetSymbolAddress((void**)&wcak, g_wcak);
    cudaGetSymbolAddress((void**)&wcav, g_wcav);
    cudaGetSymbolAddress((void**)&wff1, g_wff1);
    cudaGetSymbolAddress((void**)&wff2, g_wff2);
    cudaGetSymbolAddress((void**)&xt,   g_xt);
    cudaGetSymbolAddress((void**)&enct, g_enct);

    cudaMemcpyAsync(out, x, sizeof(float) * Bn * Tn * Cn, cudaMemcpyDeviceToDevice);

    const int nAct = Bn * Tn * Cn;
    cvt_kernel<<<(nAct + 255) / 256, 256>>>(x, xt, nAct);
    cvt_kernel<<<(nAct + 255) / 256, 256>>>(enc, enct, nAct);
    const int nQW = Ln * Hn * Cn * DHn;
    cvt_qkvw_kernel<<<nQW / 256, 256>>>(sa_wq, wsaq);
    cvt_qkvw_kernel<<<nQW / 256, 256>>>(sa_wk, wsak);
    cvt_qkvw_kernel<<<nQW / 256, 256>>>(sa_wv, wsav);
    cvt_qkvw_kernel<<<nQW / 256, 256>>>(ca_wq, wcaq);
    cvt_qkvw_kernel<<<nQW / 256, 256>>>(ca_wk, wcak);
    cvt_qkvw_kernel<<<nQW / 256, 256>>>(ca_wv, wcav);
    const int nFW = Ln * Cn * FFn;
    cvt_kernel<<<(nFW + 255) / 256, 256>>>(ff_w1, wff1, nFW);
    cvt_kernel<<<(nFW + 255) / 256, 256>>>(ff_w2, wff2, nFW);

    const size_t WSTRIDE = (size_t)Cn * 512;
    const size_t BSTRIDE = (size_t)Hn * DHn;

    for (int l = 0; l < Ln; l++) {
        // ---- self attention ----
        gemm_qkv_kernel<<<dim3(4, 64, 3), 256, GEMM_SMEM>>>(xt, xt,
            wsaq + l * WSTRIDE, wsak + l * WSTRIDE, wsav + l * WSTRIDE,
            sa_bq + l * BSTRIDE, sa_bk + l * BSTRIDE, sa_bv + l * BSTRIDE);
        attn_kernel<<<Bn * Hn, 256, ATTN_SMEM>>>(out);
        ln_norm_kernel<<<dim3(8, Bn), 256>>>(out, 8);

        // ---- cross attention ----
        gemm_qkv_kernel<<<dim3(4, 64, 3), 256, GEMM_SMEM>>>(xt, enct,
            wcaq + l * WSTRIDE, wcak + l * WSTRIDE, wcav + l * WSTRIDE,
            ca_bq + l * BSTRIDE, ca_bk + l * BSTRIDE, ca_bv + l * BSTRIDE);
        attn_kernel<<<Bn * Hn, 256, ATTN_SMEM>>>(out);
        ln_norm_kernel<<<dim3(8, Bn), 256>>>(out, 8);

        // ---- feed forward ----
        gemm_ff1_kernel<<<dim3(FFn / 128, (Bn * Tn) / 128), 256, GEMM_SMEM>>>(
            xt, wff1 + (size_t)l * Cn * FFn, ff_b1 + (size_t)l * FFn);
        gemm_ff2_kernel<<<dim3(Cn / 128, (Bn * Tn) / 128), 256, GEMM_SMEM>>>(
            wff2 + (size_t)l * FFn * Cn, ff_b2 + (size_t)l * Cn, out);
        ln_norm_kernel<<<dim3(8, Bn), 256>>>(out, 4);
    }
}